// round 9
// baseline (speedup 1.0000x reference)
#include <cuda_runtime.h>
#include <cuda_fp16.h>
#include <stdint.h>
#include <math.h>

#define NB 128
#define NI 1152
#define IC 32                   // i per k_hat CTA
#define ICHUNKS (NI/IC)         // 36
#define BC 8                    // b per k_hat CTA (4 pairs) — halves x-smem reads
#define SLOTS 48                // i-slots in k_route (24 warps x 2)
#define STEPS (NI/SLOTS)        // 24

// Scratch (static device globals; no runtime allocation)
__device__ __half g_hat[(size_t)NB * NI * 256];   // [b][i][n*16+e], 75.5 MB
__device__ float  g_s0p[(size_t)ICHUNKS * NB * 256];

// ---- packed f32x2 helpers (Blackwell FFMA2 via PTX) ----
__device__ __forceinline__ uint64_t pk(float a, float b) {
    uint64_t r; asm("mov.b64 %0, {%1,%2};" : "=l"(r) : "f"(a), "f"(b)); return r;
}
__device__ __forceinline__ void unpk(uint64_t v, float& lo, float& hi) {
    asm("mov.b64 {%0,%1}, %2;" : "=f"(lo), "=f"(hi) : "l"(v));
}
__device__ __forceinline__ uint64_t mul2(uint64_t a, uint64_t b) {
    uint64_t r; asm("mul.rn.f32x2 %0, %1, %2;" : "=l"(r) : "l"(a), "l"(b)); return r;
}
__device__ __forceinline__ void fma2(uint64_t& d, uint64_t a, uint64_t b) {
    asm("fma.rn.f32x2 %0, %1, %2, %3;" : "=l"(d) : "l"(a), "l"(b), "l"(d));
}
__device__ __forceinline__ void add2(uint64_t& d, uint64_t a) {
    asm("add.rn.f32x2 %0, %1, %2;" : "=l"(d) : "l"(a), "l"(d));
}

// ---------------------------------------------------------------------------
// k_hat: hat[b,i,n,e] = sum_d x[b,i,d]*W[n,i,e,d], fp16 out.
// grid (36 i-chunks of 32, 16 b-blocks of 8), 256 threads: t = n*16 + e.
// Batch pairs via packed f32x2 FMA; 4 pairs per CTA (256B x-smem/thread/i).
// Emits iter-0 partials per chunk (36 chunks).
// ---------------------------------------------------------------------------
__global__ void __launch_bounds__(256) k_hat(const float* __restrict__ x,
                                             const float* __restrict__ W) {
    __shared__ uint64_t sxp[4][IC][8];   // [b-pair][i][d] = (x_b, x_b+1), 8KB
    const int t  = threadIdx.x;
    const int i0 = blockIdx.x * IC;
    const int b0 = blockIdx.y * BC;

    for (int idx = t; idx < 4 * IC * 8; idx += 256) {
        int b2 = idx >> 8, rem = idx & 255;
        int ii = rem >> 3, d = rem & 7;
        float va = x[((size_t)(b0 + 2*b2    ) * NI + i0 + ii) * 8 + d];
        float vb = x[((size_t)(b0 + 2*b2 + 1) * NI + i0 + ii) * 8 + d];
        sxp[b2][ii][d] = pk(va, vb);
    }
    __syncthreads();

    const float4* wp = reinterpret_cast<const float4*>(W)
                     + ((size_t)((t >> 4) * NI + i0) * 16 + (t & 15)) * 2;

    uint64_t s0[4];
#pragma unroll
    for (int k = 0; k < 4; ++k) s0[k] = 0ull;

    float4 wa = wp[0], wb = wp[1];
    for (int i = 0; i < IC; ++i) {
        float4 na, nb;
        if (i + 1 < IC) { na = wp[32]; nb = wp[33]; }
        wp += 32;

        uint64_t ws[8];
        ws[0] = pk(wa.x, wa.x); ws[1] = pk(wa.y, wa.y);
        ws[2] = pk(wa.z, wa.z); ws[3] = pk(wa.w, wa.w);
        ws[4] = pk(wb.x, wb.x); ws[5] = pk(wb.y, wb.y);
        ws[6] = pk(wb.z, wb.z); ws[7] = pk(wb.w, wb.w);

#pragma unroll
        for (int b2 = 0; b2 < 4; ++b2) {
            const ulonglong2* xp2 = reinterpret_cast<const ulonglong2*>(&sxp[b2][i][0]);
            ulonglong2 q0 = xp2[0], q1 = xp2[1];   // 4x LDS.128
            ulonglong2 q2 = xp2[2], q3 = xp2[3];
            uint64_t acc = mul2(ws[0], q0.x);
            fma2(acc, ws[1], q0.y);
            fma2(acc, ws[2], q1.x);
            fma2(acc, ws[3], q1.y);
            fma2(acc, ws[4], q2.x);
            fma2(acc, ws[5], q2.y);
            fma2(acc, ws[6], q3.x);
            fma2(acc, ws[7], q3.y);
            add2(s0[b2], acc);
            float lo, hi; unpk(acc, lo, hi);
            size_t base = ((size_t)(b0 + 2*b2) * NI + i0 + i) * 256 + t;
            g_hat[base]                    = __float2half_rn(lo);
            g_hat[base + (size_t)NI * 256] = __float2half_rn(hi);
        }
        wa = na; wb = nb;
    }
#pragma unroll
    for (int b2 = 0; b2 < 4; ++b2) {
        float lo, hi; unpk(s0[b2], lo, hi);
        g_s0p[((size_t)blockIdx.x * NB + b0 + 2*b2    ) * 256 + t] = lo;
        g_s0p[((size_t)blockIdx.x * NB + b0 + 2*b2 + 1) * 256 + t] = hi;
    }
}

// squash along e via warp butterfly over low 4 lane bits (t = n*16+e)
__device__ __forceinline__ float squash_val(float sv) {
    float sq = sv * sv;
    sq += __shfl_xor_sync(0xffffffffu, sq, 1);
    sq += __shfl_xor_sync(0xffffffffu, sq, 2);
    sq += __shfl_xor_sync(0xffffffffu, sq, 4);
    sq += __shfl_xor_sync(0xffffffffu, sq, 8);
    float scale = sq / ((1.f + sq) * sqrtf(sq));
    return sv * scale;
}

// One i: fp16 hat fragment -> logit dot (packed), softmax over n (4 shfl),
// packed-fma accumulate into sacc.
__device__ __forceinline__ void step_i(uint4 A0, uint4 A1,
                                       const uint64_t vecp[8], uint64_t sacc[8]) {
    uint64_t fp[8];
    const __half2* ha = reinterpret_cast<const __half2*>(&A0);
#pragma unroll
    for (int j = 0; j < 4; ++j) { float2 v = __half22float2(ha[j]); fp[j] = pk(v.x, v.y); }
    const __half2* hb = reinterpret_cast<const __half2*>(&A1);
#pragma unroll
    for (int j = 0; j < 4; ++j) { float2 v = __half22float2(hb[j]); fp[4+j] = pk(v.x, v.y); }

    uint64_t dacc = mul2(vecp[0], fp[0]);
#pragma unroll
    for (int j = 1; j < 8; ++j) fma2(dacc, vecp[j], fp[j]);
    float dlo, dhi; unpk(dacc, dlo, dhi);
    float E = __expf(dlo + dhi);
    float den = E;
    den += __shfl_xor_sync(0xffffffffu, den, 1);
    den += __shfl_xor_sync(0xffffffffu, den, 2);
    den += __shfl_xor_sync(0xffffffffu, den, 4);
    den += __shfl_xor_sync(0xffffffffu, den, 8);
    float c = __fdividef(E, den);
    uint64_t cp = pk(c, c);
#pragma unroll
    for (int j = 0; j < 8; ++j) fma2(sacc[j], cp, fp[j]);
}

// One full sweep over all NI i's. st = +S (forward) or -S (reverse, for L2
// temporal locality on the second pass). p0 = this thread's FIRST element in
// traversal order. 2-step unroll, 4 LDG.128 in flight per lane.
__device__ __forceinline__ void sweep(const uint4* p, int st,
                                      const uint64_t vecp[8],
                                      int n, int slot, float sRed[SLOTS][256]) {
    uint64_t sacc[8];
#pragma unroll
    for (int j = 0; j < 8; ++j) sacc[j] = 0ull;

    uint4 A0 = p[0], A1 = p[1], B0 = p[st], B1 = p[st + 1];
#pragma unroll 2
    for (int s = 0; s < STEPS; s += 2) {
        uint4 C0, C1, D0, D1;
        if (s + 2 < STEPS) {
            C0 = p[2*st]; C1 = p[2*st + 1];
            D0 = p[3*st]; D1 = p[3*st + 1];
        }
        p += 2 * st;
        step_i(A0, A1, vecp, sacc);
        step_i(B0, B1, vecp, sacc);
        A0 = C0; A1 = C1; B0 = D0; B1 = D1;
    }
#pragma unroll
    for (int j = 0; j < 8; ++j) {
        float lo, hi; unpk(sacc[j], lo, hi);
        sRed[slot][n * 16 + 2*j]     = lo;
        sRed[slot][n * 16 + 2*j + 1] = hi;
    }
}

// ---------------------------------------------------------------------------
// k_route: all routing in one kernel, one CTA per batch. grid 128, 768 thr.
// head(out0) -> pass1 (forward) -> out1 -> pass2 (REVERSE: starts on the
// L2-hot region pass1 touched last) -> final squash -> out.
// ---------------------------------------------------------------------------
__global__ void __launch_bounds__(768) k_route(const float* __restrict__ Bias,
                                               float* __restrict__ out) {
    __shared__ float sVec[256];
    __shared__ float sOut0[256];
    __shared__ float sRed[SLOTS][256];   // 48KB

    const int b = blockIdx.x, t = threadIdx.x;
    const int warp = t >> 5, lane = t & 31;
    const int n = lane & 15, islot = lane >> 4;
    const int slot = warp * 2 + islot;

    // ---- head: out0 = squash(sum_i hat /16 + Bias) ----
    if (t < 256) {
        float sv = 0.f;
        for (int c = 0; c < ICHUNKS; ++c)
            sv += g_s0p[((size_t)c * NB + b) * 256 + t];
        sv = sv * (1.f / 16.f) + Bias[t];
        float o = squash_val(sv);
        sOut0[t] = o; sVec[t] = o;
    }
    __syncthreads();

    const int S = SLOTS * 32;
    const uint4* pF = reinterpret_cast<const uint4*>(g_hat)
                    + ((size_t)b * NI + slot) * 32 + n * 2;     // forward start
    const uint4* pR = pF + (size_t)(STEPS - 1) * S;             // reverse start

    uint64_t vecp[8];
#pragma unroll
    for (int j = 0; j < 8; ++j)
        vecp[j] = pk(sVec[n * 16 + 2*j], sVec[n * 16 + 2*j + 1]);

    // ---- pass 1: b1 = out0 . hat (forward) ----
    sweep(pF, S, vecp, n, slot, sRed);
    __syncthreads();
    if (t < 256) {
        float sv = 0.f;
#pragma unroll
        for (int w = 0; w < SLOTS; ++w) sv += sRed[w][t];
        sv += Bias[t];
        sVec[t] = sOut0[t] + squash_val(sv);   // telescoped vec = out0 + out1
    }
    __syncthreads();

#pragma unroll
    for (int j = 0; j < 8; ++j)
        vecp[j] = pk(sVec[n * 16 + 2*j], sVec[n * 16 + 2*j + 1]);

    // ---- pass 2: b2 = (out0+out1) . hat (reverse), final squash ----
    sweep(pR, -S, vecp, n, slot, sRed);
    __syncthreads();
    if (t < 256) {
        float sv = 0.f;
#pragma unroll
        for (int w = 0; w < SLOTS; ++w) sv += sRed[w][t];
        sv += Bias[t];
        out[b * 256 + t] = squash_val(sv);
    }
}

extern "C" void kernel_launch(void* const* d_in, const int* in_sizes, int n_in,
                              void* d_out, int out_size) {
    const float* x    = (const float*)d_in[0];   // [128,1152,8]
    const float* W    = (const float*)d_in[1];   // [16,1152,16,8]
    const float* Bias = (const float*)d_in[2];   // [16,16]
    float* out = (float*)d_out;                  // [128,16,16]

    k_hat<<<dim3(ICHUNKS, NB / BC), 256>>>(x, W);   // (36,16) = 576 CTAs
    k_route<<<NB, 768>>>(Bias, out);                // 128 CTAs, 1 per batch
}